// round 1
// baseline (speedup 1.0000x reference)
#include <cuda_runtime.h>
#include <cstdint>

// ---------------- problem constants ----------------
#define NB   8
#define NT   336
#define NN   1024
#define FREQ 42
#define SEG  8
#define DC   64
#define DM   128
#define TREC 41          // FREQ-1, stconv time length for rec path
#define NSTEP 12
#define MAXK 11
#define ALPHA 0.05f

// ---------------- scratch layout (floats) ----------------
// all sizes multiples of 64
static const size_t OFF_A1   = 0;                        // 1024*1024
static const size_t OFF_A2   = OFF_A1   + 1048576;
static const size_t OFF_WCT  = OFF_A2   + 1048576;       // 11*64*64
static const size_t OFF_BSUM = OFF_WCT  + 45056;         // 64
static const size_t OFF_RES  = OFF_BSUM + 64;            // 8*42*1024*64
static const size_t OFF_CONV = OFF_RES  + 22020096;      // 8*41*1024*64
static const size_t OFF_H1A  = OFF_CONV + 21495808;
static const size_t OFF_H2A  = OFF_H1A  + 21495808;
static const size_t OFF_H1B  = OFF_H2A  + 21495808;
static const size_t OFF_H2B  = OFF_H1B  + 21495808;
static const size_t OFF_STOUT= OFF_H2B  + 21495808;
static const size_t OFF_CUR  = OFF_STOUT+ 21495808;      // 8*23*1024*64
static const size_t OFF_TCL  = OFF_CUR  + 12058624;      // 8*1024*64
static const size_t OFF_PH1A = OFF_TCL  + 524288;
static const size_t OFF_PH1B = OFF_PH1A + 524288;
static const size_t OFF_PH2A = OFF_PH1B + 524288;
static const size_t OFF_PH2B = OFF_PH2A + 524288;
static const size_t SCRATCH_TOTAL = OFF_PH2B + 524288;   // 167,817,280 floats

__device__ float g_scratch[SCRATCH_TOTAL];

// ================= common 64x64x64 GEMM micro-kernel =================
// 256 threads, 4x4 microtile per thread, shared tiles stored k-major, pad 68.

__device__ __forceinline__ void loadA_T(float (*As)[68], const float* __restrict__ src,
                                        int ld, int tid) {
    // src: tile origin, rows m (0..63) x k contiguous (64)
#pragma unroll
    for (int i = 0; i < 4; i++) {
        int li = tid + i * 256;
        int r = li >> 4, c4 = li & 15;
        float4 v = *(const float4*)&src[(size_t)r * ld + c4 * 4];
        As[c4 * 4 + 0][r] = v.x;
        As[c4 * 4 + 1][r] = v.y;
        As[c4 * 4 + 2][r] = v.z;
        As[c4 * 4 + 3][r] = v.w;
    }
}

__device__ __forceinline__ void loadB_D(float (*Bs)[68], const float* __restrict__ src,
                                        int ld, int tid) {
    // src: tile origin, rows k (0..63) x n contiguous (64)
#pragma unroll
    for (int i = 0; i < 4; i++) {
        int li = tid + i * 256;
        int r = li >> 4, c4 = li & 15;
        *(float4*)&Bs[r][c4 * 4] = *(const float4*)&src[(size_t)r * ld + c4 * 4];
    }
}

__device__ __forceinline__ void mm64(const float (*As)[68], const float (*Bs)[68],
                                     float acc[4][4], int tx, int ty) {
#pragma unroll
    for (int k = 0; k < 64; k++) {
        float4 a = *(const float4*)&As[k][ty * 4];
        float4 b = *(const float4*)&Bs[k][tx * 4];
        float av[4] = {a.x, a.y, a.z, a.w};
        float bv[4] = {b.x, b.y, b.z, b.w};
#pragma unroll
        for (int i = 0; i < 4; i++)
#pragma unroll
            for (int j = 0; j < 4; j++)
                acc[i][j] = fmaf(av[i], bv[j], acc[i][j]);
    }
}

// ================= adjacency normalization =================
__global__ void k_norm_adj(const float* __restrict__ adj,
                           float* __restrict__ a1, float* __restrict__ a2) {
    int v = blockIdx.x;
    int tid = threadIdx.x;
    __shared__ float r1[256], r2[256];
    float s1 = 0.f, s2 = 0.f;
    for (int n = tid; n < NN; n += 256) {
        s1 += adj[(size_t)v * NN + n];
        s2 += adj[(size_t)n * NN + v];
    }
    r1[tid] = s1; r2[tid] = s2;
    __syncthreads();
    for (int off = 128; off > 0; off >>= 1) {
        if (tid < off) { r1[tid] += r1[tid + off]; r2[tid] += r2[tid + off]; }
        __syncthreads();
    }
    float inv1 = 1.f / (r1[0] + 1.f);
    float inv2 = 1.f / (r2[0] + 1.f);
    for (int n = tid; n < NN; n += 256) {
        float d = (n == v) ? 1.f : 0.f;
        a1[(size_t)v * NN + n] = (adj[(size_t)v * NN + n] + d) * inv1;
        a2[(size_t)v * NN + n] = (adj[(size_t)n * NN + v] + d) * inv2;
    }
}

// ================= combine conv weights =================
// wcT[dt][c][o] = sum_{i >= |dt-5|} conv_wi[o][c][dt-5+i] ; bsum[o] = sum_i b_i[o]
__global__ void k_comb_w(const float* w0, const float* w1, const float* w2,
                         const float* w3, const float* w4, const float* w5,
                         const float* cb0, const float* cb1, const float* cb2,
                         const float* cb3, const float* cb4, const float* cb5,
                         float* __restrict__ wcT, float* __restrict__ bsum) {
    int idx = blockIdx.x * 256 + threadIdx.x;
    if (idx >= 11 * 64 * 64) return;
    int o = idx & 63;
    int c = (idx >> 6) & 63;
    int dt = idx >> 12;
    int dv = dt - 5;
    int ad = dv < 0 ? -dv : dv;
    const float* ws[6] = {w0, w1, w2, w3, w4, w5};
    float acc = 0.f;
    for (int i = ad; i < 6; i++) {
        int K = 2 * i + 1;
        acc += ws[i][(size_t)(o * 64 + c) * K + (dv + i)];
    }
    wcT[((size_t)dt * 64 + c) * 64 + o] = acc;
    if (dt == 0 && c == 0)
        bsum[o] = cb0[o] + cb1[o] + cb2[o] + cb3[o] + cb4[o] + cb5[o];
}

// ================= encoder MLP: (B,42,N,8) -> (B,42,N,64) =================
__global__ void __launch_bounds__(256) k_enc(const float* __restrict__ x,
        const float* __restrict__ w1, const float* __restrict__ b1,
        const float* __restrict__ w2, const float* __restrict__ b2,
        float* __restrict__ out) {
    int n0 = blockIdx.x * 64;
    int f  = blockIdx.y;
    int b  = blockIdx.z;
    __shared__ float xs[64][8];
    __shared__ float hs[64][129];
    __shared__ float w1s[8 * 128];
    int tid = threadIdx.x;
    for (int i = tid; i < 1024; i += 256) w1s[i] = w1[i];
    for (int i = tid; i < 512; i += 256) {
        int s = i >> 6, r = i & 63;
        xs[r][s] = x[((size_t)(b * NT) + f * SEG + s) * NN + n0 + r];
    }
    __syncthreads();
    {
        int r = tid >> 2;
        int j0 = (tid & 3) * 32;
        float xv[8];
#pragma unroll
        for (int s = 0; s < 8; s++) xv[s] = xs[r][s];
        for (int j = j0; j < j0 + 32; j++) {
            float h = b1[j];
#pragma unroll
            for (int s = 0; s < 8; s++) h = fmaf(xv[s], w1s[s * 128 + j], h);
            hs[r][j] = fmaxf(h, 0.f);
        }
    }
    __syncthreads();
    {
        int r = tid >> 2;
        int d0 = (tid & 3) * 16;
        for (int d = d0; d < d0 + 16; d++) {
            float acc = b2[d];
#pragma unroll
            for (int j = 0; j < 128; j++) acc = fmaf(hs[r][j], w2[j * 64 + d], acc);
            out[(((size_t)b * FREQ + f) * NN + n0 + r) * 64 + d] = acc;
        }
    }
}

// ================= t_inception (rec path) =================
// out[b,t,n,:] = (bsum + sum_dt Wc[dt] @ res[b,t+dt-5,n,:]) / 6 , t in [0,41)
__global__ void __launch_bounds__(256) k_tconv(const float* __restrict__ res,
        const float* __restrict__ wcT, const float* __restrict__ bsum,
        float* __restrict__ out) {
    int n0 = blockIdx.x * 64;
    int bt = blockIdx.y;
    int b = bt / TREC, t = bt % TREC;
    __shared__ float As[64][68];
    __shared__ float Bs[64][68];
    int tid = threadIdx.x;
    int tx = tid & 15, ty = tid >> 4;
    float acc[4][4] = {};
    for (int dt = 0; dt < 11; dt++) {
        int ts = t + dt - 5;
        if (ts < 0 || ts >= TREC) continue;   // uniform across block
        loadA_T(As, &res[(((size_t)b * FREQ + ts) * NN + n0) * 64], 64, tid);
        loadB_D(Bs, &wcT[(size_t)dt * 64 * 64], 64, tid);
        __syncthreads();
        mm64(As, Bs, acc, tx, ty);
        __syncthreads();
    }
    const float inv6 = 1.f / 6.f;
#pragma unroll
    for (int i = 0; i < 4; i++) {
        int m = ty * 4 + i;
#pragma unroll
        for (int j = 0; j < 4; j++) {
            int d = tx * 4 + j;
            out[(((size_t)bt) * NN + n0 + m) * 64 + d] = (acc[i][j] + bsum[d]) * inv6;
        }
    }
}

// ================= mixprop propagation step =================
// hout = ALPHA*xin + (1-ALPHA) * A @ hin, per bt slice (1024x64)
__global__ void __launch_bounds__(256) k_prop(const float* __restrict__ A,
        const float* __restrict__ hin, const float* __restrict__ xin,
        float* __restrict__ hout) {
    int m0 = blockIdx.x * 64;
    size_t base = (size_t)blockIdx.y * (NN * 64);
    __shared__ float As[64][68];
    __shared__ float Bs[64][68];
    int tid = threadIdx.x;
    int tx = tid & 15, ty = tid >> 4;
    float acc[4][4] = {};
    for (int k0 = 0; k0 < NN; k0 += 64) {
        loadA_T(As, &A[(size_t)m0 * NN + k0], NN, tid);
        loadB_D(Bs, &hin[base + (size_t)k0 * 64], 64, tid);
        __syncthreads();
        mm64(As, Bs, acc, tx, ty);
        __syncthreads();
    }
#pragma unroll
    for (int i = 0; i < 4; i++) {
        int v = m0 + ty * 4 + i;
#pragma unroll
        for (int j = 0; j < 4; j++) {
            int d = tx * 4 + j;
            size_t idx = base + (size_t)v * 64 + d;
            hout[idx] = ALPHA * xin[idx] + (1.f - ALPHA) * acc[i][j];
        }
    }
}

// ================= mixprop combine + residual =================
// out = [x,h1a,h2a]@g1w + g1b + [x,h1b,h2b]@g2w + g2b + resid
__global__ void __launch_bounds__(256) k_combine(const float* __restrict__ x,
        const float* __restrict__ h1a, const float* __restrict__ h2a,
        const float* __restrict__ h1b, const float* __restrict__ h2b,
        const float* __restrict__ g1w, const float* __restrict__ g1b,
        const float* __restrict__ g2w, const float* __restrict__ g2b,
        const float* __restrict__ resid, float* __restrict__ out,
        int rdiv, int rmul, int roff,
        int odiv, int omul, int ooff) {
    int n0 = blockIdx.x * 64;
    int bt = blockIdx.y;
    size_t base = (size_t)bt * (NN * 64);
    const float* srcs[6] = {x, h1a, h2a, x, h1b, h2b};
    const float* wgt[6]  = {g1w, g1w + 4096, g1w + 8192, g2w, g2w + 4096, g2w + 8192};
    __shared__ float As[64][68];
    __shared__ float Bs[64][68];
    int tid = threadIdx.x;
    int tx = tid & 15, ty = tid >> 4;
    float acc[4][4] = {};
    for (int p = 0; p < 6; p++) {
        loadA_T(As, &srcs[p][base + (size_t)n0 * 64], 64, tid);
        loadB_D(Bs, wgt[p], 64, tid);
        __syncthreads();
        mm64(As, Bs, acc, tx, ty);
        __syncthreads();
    }
    int rrow = (bt / rdiv) * rmul + (bt % rdiv) + roff;
    int orow = (bt / odiv) * omul + (bt % odiv) + ooff;
#pragma unroll
    for (int i = 0; i < 4; i++) {
        int m = n0 + ty * 4 + i;
#pragma unroll
        for (int j = 0; j < 4; j++) {
            int d = tx * 4 + j;
            float r = resid[((size_t)rrow * NN + m) * 64 + d];
            out[((size_t)orow * NN + m) * 64 + d] = acc[i][j] + g1b[d] + g2b[d] + r;
        }
    }
}

// ================= AR: last-timestep t_inception =================
// out[b,n,o] = (bsum + sum_{j=0}^{5} Wc[j] @ cur[b, s+5+j, n, :]) / 6
__global__ void __launch_bounds__(256) k_tcl(const float* __restrict__ cur,
        const float* __restrict__ wcT, const float* __restrict__ bsum,
        float* __restrict__ out, int s) {
    int row0 = blockIdx.x * 64;      // over 8*1024 rows
    int b = row0 >> 10;
    int n0 = row0 & 1023;
    __shared__ float As[64][68];
    __shared__ float Bs[64][68];
    int tid = threadIdx.x;
    int tx = tid & 15, ty = tid >> 4;
    float acc[4][4] = {};
    for (int j = 0; j < 6; j++) {
        loadA_T(As, &cur[(((size_t)b * 23 + s + 5 + j) * NN + n0) * 64], 64, tid);
        loadB_D(Bs, &wcT[(size_t)j * 64 * 64], 64, tid);
        __syncthreads();
        mm64(As, Bs, acc, tx, ty);
        __syncthreads();
    }
    const float inv6 = 1.f / 6.f;
#pragma unroll
    for (int i = 0; i < 4; i++) {
        int m = row0 + ty * 4 + i;
#pragma unroll
        for (int j = 0; j < 4; j++) {
            int d = tx * 4 + j;
            out[(size_t)m * 64 + d] = (acc[i][j] + bsum[d]) * inv6;
        }
    }
}

// ================= AR cur-buffer init: cur[:,0:11] = res[:,31:42] =================
__global__ void k_cur_init(const float* __restrict__ res, float* __restrict__ cur) {
    size_t total = (size_t)NB * MAXK * NN * 64;
    for (size_t idx = (size_t)blockIdx.x * blockDim.x + threadIdx.x; idx < total;
         idx += (size_t)gridDim.x * blockDim.x) {
        int d = idx & 63;
        int n = (idx >> 6) & 1023;
        int j = (int)((idx >> 16) % MAXK);
        int b = (int)(idx / ((size_t)MAXK << 16));
        cur[(((size_t)b * 23 + j) * NN + n) * 64 + d] =
            res[(((size_t)b * FREQ + 31 + j) * NN + n) * 64 + d];
    }
}

// ================= decoder MLP for rec =================
__global__ void __launch_bounds__(256) k_dec_rec(const float* __restrict__ res,
        const float* __restrict__ stout,
        const float* __restrict__ w1, const float* __restrict__ b1,
        const float* __restrict__ w2, const float* __restrict__ b2,
        float* __restrict__ out) {
    int n0 = blockIdx.x * 64;
    int f  = blockIdx.y;
    int b  = blockIdx.z;
    const float* src = (f == 0)
        ? &res[(((size_t)b * FREQ) * NN + n0) * 64]
        : &stout[(((size_t)b * TREC + f - 1) * NN + n0) * 64];
    __shared__ float hs[64][129];
    int tid = threadIdx.x;
    {
        int r = tid >> 2;
        int j0 = (tid & 3) * 32;
        const float* xr = &src[(size_t)r * 64];
        for (int j = j0; j < j0 + 32; j++) {
            float h = b1[j];
#pragma unroll
            for (int c = 0; c < 64; c++) h = fmaf(xr[c], w1[c * 128 + j], h);
            hs[r][j] = fmaxf(h, 0.f);
        }
    }
    __syncthreads();
    for (int o = tid; o < 512; o += 256) {
        int r = o & 63, s = o >> 6;
        float acc = b2[s];
#pragma unroll
        for (int j = 0; j < 128; j++) acc = fmaf(hs[r][j], w2[j * 8 + s], acc);
        out[((size_t)b * NT + f * SEG + s) * NN + n0 + r] = acc;
    }
}

// ================= decoder MLP for pred (with the reference's direct reshape) =================
// pred flat per batch: t*8192 + n*8 + s
__global__ void __launch_bounds__(256) k_dec_pred(const float* __restrict__ cur,
        const float* __restrict__ w1, const float* __restrict__ b1,
        const float* __restrict__ w2, const float* __restrict__ b2,
        float* __restrict__ out) {
    int n0 = blockIdx.x * 64;
    int t  = blockIdx.y;
    int b  = blockIdx.z;
    const float* src = &cur[(((size_t)b * 23 + MAXK + t) * NN + n0) * 64];
    __shared__ float hs[64][129];
    int tid = threadIdx.x;
    {
        int r = tid >> 2;
        int j0 = (tid & 3) * 32;
        const float* xr = &src[(size_t)r * 64];
        for (int j = j0; j < j0 + 32; j++) {
            float h = b1[j];
#pragma unroll
            for (int c = 0; c < 64; c++) h = fmaf(xr[c], w1[c * 128 + j], h);
            hs[r][j] = fmaxf(h, 0.f);
        }
    }
    __syncthreads();
    for (int o = tid; o < 512; o += 256) {
        int r = o >> 3, s = o & 7;
        float acc = b2[s];
#pragma unroll
        for (int j = 0; j < 128; j++) acc = fmaf(hs[r][j], w2[j * 8 + s], acc);
        out[(size_t)b * (NSTEP * SEG * NN) + (size_t)t * 8192 + (size_t)(n0 + r) * 8 + s] = acc;
    }
}

// ================= host launcher =================
extern "C" void kernel_launch(void* const* d_in, const int* in_sizes, int n_in,
                              void* d_out, int out_size) {
    (void)in_sizes; (void)n_in; (void)out_size;
    const float* x_diff = (const float*)d_in[0];
    const float* adj    = (const float*)d_in[1];
    const float* enc_w1 = (const float*)d_in[2];
    const float* enc_b1 = (const float*)d_in[3];
    const float* enc_w2 = (const float*)d_in[4];
    const float* enc_b2 = (const float*)d_in[5];
    const float* dec_w1 = (const float*)d_in[6];
    const float* dec_b1 = (const float*)d_in[7];
    const float* dec_w2 = (const float*)d_in[8];
    const float* dec_b2 = (const float*)d_in[9];
    const float* g1_w   = (const float*)d_in[10];
    const float* g1_b   = (const float*)d_in[11];
    const float* g2_w   = (const float*)d_in[12];
    const float* g2_b   = (const float*)d_in[13];
    const float* cw[6], *cb[6];
    for (int i = 0; i < 6; i++) {
        cw[i] = (const float*)d_in[14 + 2 * i];
        cb[i] = (const float*)d_in[15 + 2 * i];
    }

    float* scratch = nullptr;
    cudaGetSymbolAddress((void**)&scratch, g_scratch);
    float* a1    = scratch + OFF_A1;
    float* a2    = scratch + OFF_A2;
    float* wcT   = scratch + OFF_WCT;
    float* bsum  = scratch + OFF_BSUM;
    float* res   = scratch + OFF_RES;
    float* conv  = scratch + OFF_CONV;
    float* h1a   = scratch + OFF_H1A;
    float* h2a   = scratch + OFF_H2A;
    float* h1b   = scratch + OFF_H1B;
    float* h2b   = scratch + OFF_H2B;
    float* stout = scratch + OFF_STOUT;
    float* cur   = scratch + OFF_CUR;
    float* tcl   = scratch + OFF_TCL;
    float* ph1a  = scratch + OFF_PH1A;
    float* ph1b  = scratch + OFF_PH1B;
    float* ph2a  = scratch + OFF_PH2A;
    float* ph2b  = scratch + OFF_PH2B;

    float* rec_out  = (float*)d_out;
    float* pred_out = rec_out + (size_t)NB * NT * NN;

    // ---- preprocessing ----
    k_norm_adj<<<NN, 256>>>(adj, a1, a2);
    k_comb_w<<<(11 * 64 * 64 + 255) / 256, 256>>>(cw[0], cw[1], cw[2], cw[3], cw[4], cw[5],
                                                  cb[0], cb[1], cb[2], cb[3], cb[4], cb[5],
                                                  wcT, bsum);
    // ---- encoder ----
    k_enc<<<dim3(16, FREQ, NB), 256>>>(x_diff, enc_w1, enc_b1, enc_w2, enc_b2, res);

    // ---- rec-path stconv ----
    dim3 gRec(16, NB * TREC);
    k_tconv<<<gRec, 256>>>(res, wcT, bsum, conv);
    k_prop<<<gRec, 256>>>(a1, conv, conv, h1a);
    k_prop<<<gRec, 256>>>(a2, conv, conv, h1b);
    k_prop<<<gRec, 256>>>(a1, h1a, conv, h2a);
    k_prop<<<gRec, 256>>>(a2, h1b, conv, h2b);
    k_combine<<<gRec, 256>>>(conv, h1a, h2a, h1b, h2b, g1_w, g1_b, g2_w, g2_b,
                             res, stout,
                             TREC, FREQ, 0,     // resid row = b*42 + t
                             TREC, TREC, 0);    // out   row = bt
    // ---- rec decoder ----
    k_dec_rec<<<dim3(16, FREQ, NB), 256>>>(res, stout, dec_w1, dec_b1, dec_w2, dec_b2, rec_out);

    // ---- autoregressive loop ----
    k_cur_init<<<4096, 256>>>(res, cur);
    dim3 gAR(16, NB);
    for (int s = 0; s < NSTEP; s++) {
        k_tcl<<<128, 256>>>(cur, wcT, bsum, tcl, s);
        k_prop<<<gAR, 256>>>(a1, tcl, tcl, ph1a);
        k_prop<<<gAR, 256>>>(a2, tcl, tcl, ph1b);
        k_prop<<<gAR, 256>>>(a1, ph1a, tcl, ph2a);
        k_prop<<<gAR, 256>>>(a2, ph1b, tcl, ph2b);
        k_combine<<<gAR, 256>>>(tcl, ph1a, ph2a, ph1b, ph2b, g1_w, g1_b, g2_w, g2_b,
                                cur, cur,
                                1, 23, s + 10,   // resid row = b*23 + s+10
                                1, 23, s + 11);  // out   row = b*23 + s+11
    }
    // ---- pred decoder ----
    k_dec_pred<<<dim3(16, NSTEP, NB), 256>>>(cur, dec_w1, dec_b1, dec_w2, dec_b2, pred_out);
}

// round 2
// speedup vs baseline: 1.0006x; 1.0006x over previous
#include <cuda_runtime.h>
#include <cstdint>

// ---------------- problem constants ----------------
#define NB   8
#define NT   336
#define NN   1024
#define FREQ 42
#define SEG  8
#define DC   64
#define DM   128
#define TREC 41          // FREQ-1, stconv time length for rec path
#define NSTEP 12
#define MAXK 11
#define ALPHA 0.05f

// ---------------- scratch layout (floats) ----------------
// all sizes multiples of 64
static const size_t OFF_A1   = 0;                        // 1024*1024
static const size_t OFF_A2   = OFF_A1   + 1048576;
static const size_t OFF_WCT  = OFF_A2   + 1048576;       // 11*64*64
static const size_t OFF_BSUM = OFF_WCT  + 45056;         // 64
static const size_t OFF_RES  = OFF_BSUM + 64;            // 8*42*1024*64
static const size_t OFF_CONV = OFF_RES  + 22020096;      // 8*41*1024*64
static const size_t OFF_H1A  = OFF_CONV + 21495808;
static const size_t OFF_H2A  = OFF_H1A  + 21495808;
static const size_t OFF_H1B  = OFF_H2A  + 21495808;
static const size_t OFF_H2B  = OFF_H1B  + 21495808;
static const size_t OFF_STOUT= OFF_H2B  + 21495808;
static const size_t OFF_CUR  = OFF_STOUT+ 21495808;      // 8*23*1024*64
static const size_t OFF_TCL  = OFF_CUR  + 12058624;      // 8*1024*64
static const size_t OFF_PH1A = OFF_TCL  + 524288;
static const size_t OFF_PH1B = OFF_PH1A + 524288;
static const size_t OFF_PH2A = OFF_PH1B + 524288;
static const size_t OFF_PH2B = OFF_PH2A + 524288;
static const size_t SCRATCH_TOTAL = OFF_PH2B + 524288;   // 167,817,280 floats

__device__ float g_scratch[SCRATCH_TOTAL];

// ================= common 64x64x64 GEMM micro-kernel =================
// 256 threads, 4x4 microtile per thread, shared tiles stored k-major, pad 68.

__device__ __forceinline__ void loadA_T(float (*As)[68], const float* __restrict__ src,
                                        int ld, int tid) {
    // src: tile origin, rows m (0..63) x k contiguous (64)
#pragma unroll
    for (int i = 0; i < 4; i++) {
        int li = tid + i * 256;
        int r = li >> 4, c4 = li & 15;
        float4 v = *(const float4*)&src[(size_t)r * ld + c4 * 4];
        As[c4 * 4 + 0][r] = v.x;
        As[c4 * 4 + 1][r] = v.y;
        As[c4 * 4 + 2][r] = v.z;
        As[c4 * 4 + 3][r] = v.w;
    }
}

__device__ __forceinline__ void loadB_D(float (*Bs)[68], const float* __restrict__ src,
                                        int ld, int tid) {
    // src: tile origin, rows k (0..63) x n contiguous (64)
#pragma unroll
    for (int i = 0; i < 4; i++) {
        int li = tid + i * 256;
        int r = li >> 4, c4 = li & 15;
        *(float4*)&Bs[r][c4 * 4] = *(const float4*)&src[(size_t)r * ld + c4 * 4];
    }
}

__device__ __forceinline__ void mm64(const float (*As)[68], const float (*Bs)[68],
                                     float acc[4][4], int tx, int ty) {
#pragma unroll
    for (int k = 0; k < 64; k++) {
        float4 a = *(const float4*)&As[k][ty * 4];
        float4 b = *(const float4*)&Bs[k][tx * 4];
        float av[4] = {a.x, a.y, a.z, a.w};
        float bv[4] = {b.x, b.y, b.z, b.w};
#pragma unroll
        for (int i = 0; i < 4; i++)
#pragma unroll
            for (int j = 0; j < 4; j++)
                acc[i][j] = fmaf(av[i], bv[j], acc[i][j]);
    }
}

// ================= adjacency normalization =================
__global__ void k_norm_adj(const float* __restrict__ adj,
                           float* __restrict__ a1, float* __restrict__ a2) {
    int v = blockIdx.x;
    int tid = threadIdx.x;
    __shared__ float r1[256], r2[256];
    float s1 = 0.f, s2 = 0.f;
    for (int n = tid; n < NN; n += 256) {
        s1 += adj[(size_t)v * NN + n];
        s2 += adj[(size_t)n * NN + v];
    }
    r1[tid] = s1; r2[tid] = s2;
    __syncthreads();
    for (int off = 128; off > 0; off >>= 1) {
        if (tid < off) { r1[tid] += r1[tid + off]; r2[tid] += r2[tid + off]; }
        __syncthreads();
    }
    float inv1 = 1.f / (r1[0] + 1.f);
    float inv2 = 1.f / (r2[0] + 1.f);
    for (int n = tid; n < NN; n += 256) {
        float d = (n == v) ? 1.f : 0.f;
        a1[(size_t)v * NN + n] = (adj[(size_t)v * NN + n] + d) * inv1;
        a2[(size_t)v * NN + n] = (adj[(size_t)n * NN + v] + d) * inv2;
    }
}

// ================= combine conv weights =================
// wcT[dt][c][o] = sum_{i >= |dt-5|} conv_wi[o][c][dt-5+i] ; bsum[o] = sum_i b_i[o]
__global__ void k_comb_w(const float* w0, const float* w1, const float* w2,
                         const float* w3, const float* w4, const float* w5,
                         const float* cb0, const float* cb1, const float* cb2,
                         const float* cb3, const float* cb4, const float* cb5,
                         float* __restrict__ wcT, float* __restrict__ bsum) {
    int idx = blockIdx.x * 256 + threadIdx.x;
    if (idx >= 11 * 64 * 64) return;
    int o = idx & 63;
    int c = (idx >> 6) & 63;
    int dt = idx >> 12;
    int dv = dt - 5;
    int ad = dv < 0 ? -dv : dv;
    const float* ws[6] = {w0, w1, w2, w3, w4, w5};
    float acc = 0.f;
    for (int i = ad; i < 6; i++) {
        int K = 2 * i + 1;
        acc += ws[i][(size_t)(o * 64 + c) * K + (dv + i)];
    }
    wcT[((size_t)dt * 64 + c) * 64 + o] = acc;
    if (dt == 0 && c == 0)
        bsum[o] = cb0[o] + cb1[o] + cb2[o] + cb3[o] + cb4[o] + cb5[o];
}

// ================= encoder MLP: (B,42,N,8) -> (B,42,N,64) =================
__global__ void __launch_bounds__(256) k_enc(const float* __restrict__ x,
        const float* __restrict__ w1, const float* __restrict__ b1,
        const float* __restrict__ w2, const float* __restrict__ b2,
        float* __restrict__ out) {
    int n0 = blockIdx.x * 64;
    int f  = blockIdx.y;
    int b  = blockIdx.z;
    __shared__ float xs[64][8];
    __shared__ float hs[64][129];
    __shared__ float w1s[8 * 128];
    int tid = threadIdx.x;
    for (int i = tid; i < 1024; i += 256) w1s[i] = w1[i];
    for (int i = tid; i < 512; i += 256) {
        int s = i >> 6, r = i & 63;
        xs[r][s] = x[((size_t)(b * NT) + f * SEG + s) * NN + n0 + r];
    }
    __syncthreads();
    {
        int r = tid >> 2;
        int j0 = (tid & 3) * 32;
        float xv[8];
#pragma unroll
        for (int s = 0; s < 8; s++) xv[s] = xs[r][s];
        for (int j = j0; j < j0 + 32; j++) {
            float h = b1[j];
#pragma unroll
            for (int s = 0; s < 8; s++) h = fmaf(xv[s], w1s[s * 128 + j], h);
            hs[r][j] = fmaxf(h, 0.f);
        }
    }
    __syncthreads();
    {
        int r = tid >> 2;
        int d0 = (tid & 3) * 16;
        for (int d = d0; d < d0 + 16; d++) {
            float acc = b2[d];
#pragma unroll
            for (int j = 0; j < 128; j++) acc = fmaf(hs[r][j], w2[j * 64 + d], acc);
            out[(((size_t)b * FREQ + f) * NN + n0 + r) * 64 + d] = acc;
        }
    }
}

// ================= t_inception (rec path) =================
// out[b,t,n,:] = (bsum + sum_dt Wc[dt] @ res[b,t+dt-5,n,:]) / 6 , t in [0,41)
__global__ void __launch_bounds__(256) k_tconv(const float* __restrict__ res,
        const float* __restrict__ wcT, const float* __restrict__ bsum,
        float* __restrict__ out) {
    int n0 = blockIdx.x * 64;
    int bt = blockIdx.y;
    int b = bt / TREC, t = bt % TREC;
    __shared__ float As[64][68];
    __shared__ float Bs[64][68];
    int tid = threadIdx.x;
    int tx = tid & 15, ty = tid >> 4;
    float acc[4][4] = {};
    for (int dt = 0; dt < 11; dt++) {
        int ts = t + dt - 5;
        if (ts < 0 || ts >= TREC) continue;   // uniform across block
        loadA_T(As, &res[(((size_t)b * FREQ + ts) * NN + n0) * 64], 64, tid);
        loadB_D(Bs, &wcT[(size_t)dt * 64 * 64], 64, tid);
        __syncthreads();
        mm64(As, Bs, acc, tx, ty);
        __syncthreads();
    }
    const float inv6 = 1.f / 6.f;
#pragma unroll
    for (int i = 0; i < 4; i++) {
        int m = ty * 4 + i;
#pragma unroll
        for (int j = 0; j < 4; j++) {
            int d = tx * 4 + j;
            out[(((size_t)bt) * NN + n0 + m) * 64 + d] = (acc[i][j] + bsum[d]) * inv6;
        }
    }
}

// ================= mixprop propagation step =================
// hout = ALPHA*xin + (1-ALPHA) * A @ hin, per bt slice (1024x64)
__global__ void __launch_bounds__(256) k_prop(const float* __restrict__ A,
        const float* __restrict__ hin, const float* __restrict__ xin,
        float* __restrict__ hout) {
    int m0 = blockIdx.x * 64;
    size_t base = (size_t)blockIdx.y * (NN * 64);
    __shared__ float As[64][68];
    __shared__ float Bs[64][68];
    int tid = threadIdx.x;
    int tx = tid & 15, ty = tid >> 4;
    float acc[4][4] = {};
    for (int k0 = 0; k0 < NN; k0 += 64) {
        loadA_T(As, &A[(size_t)m0 * NN + k0], NN, tid);
        loadB_D(Bs, &hin[base + (size_t)k0 * 64], 64, tid);
        __syncthreads();
        mm64(As, Bs, acc, tx, ty);
        __syncthreads();
    }
#pragma unroll
    for (int i = 0; i < 4; i++) {
        int v = m0 + ty * 4 + i;
#pragma unroll
        for (int j = 0; j < 4; j++) {
            int d = tx * 4 + j;
            size_t idx = base + (size_t)v * 64 + d;
            hout[idx] = ALPHA * xin[idx] + (1.f - ALPHA) * acc[i][j];
        }
    }
}

// ================= mixprop combine + residual =================
// out = [x,h1a,h2a]@g1w + g1b + [x,h1b,h2b]@g2w + g2b + resid
__global__ void __launch_bounds__(256) k_combine(const float* __restrict__ x,
        const float* __restrict__ h1a, const float* __restrict__ h2a,
        const float* __restrict__ h1b, const float* __restrict__ h2b,
        const float* __restrict__ g1w, const float* __restrict__ g1b,
        const float* __restrict__ g2w, const float* __restrict__ g2b,
        const float* __restrict__ resid, float* __restrict__ out,
        int rdiv, int rmul, int roff,
        int odiv, int omul, int ooff) {
    int n0 = blockIdx.x * 64;
    int bt = blockIdx.y;
    size_t base = (size_t)bt * (NN * 64);
    const float* srcs[6] = {x, h1a, h2a, x, h1b, h2b};
    const float* wgt[6]  = {g1w, g1w + 4096, g1w + 8192, g2w, g2w + 4096, g2w + 8192};
    __shared__ float As[64][68];
    __shared__ float Bs[64][68];
    int tid = threadIdx.x;
    int tx = tid & 15, ty = tid >> 4;
    float acc[4][4] = {};
    for (int p = 0; p < 6; p++) {
        loadA_T(As, &srcs[p][base + (size_t)n0 * 64], 64, tid);
        loadB_D(Bs, wgt[p], 64, tid);
        __syncthreads();
        mm64(As, Bs, acc, tx, ty);
        __syncthreads();
    }
    int rrow = (bt / rdiv) * rmul + (bt % rdiv) + roff;
    int orow = (bt / odiv) * omul + (bt % odiv) + ooff;
#pragma unroll
    for (int i = 0; i < 4; i++) {
        int m = n0 + ty * 4 + i;
#pragma unroll
        for (int j = 0; j < 4; j++) {
            int d = tx * 4 + j;
            float r = resid[((size_t)rrow * NN + m) * 64 + d];
            out[((size_t)orow * NN + m) * 64 + d] = acc[i][j] + g1b[d] + g2b[d] + r;
        }
    }
}

// ================= AR: last-timestep t_inception =================
// out[b,n,o] = (bsum + sum_{j=0}^{5} Wc[j] @ cur[b, s+5+j, n, :]) / 6
__global__ void __launch_bounds__(256) k_tcl(const float* __restrict__ cur,
        const float* __restrict__ wcT, const float* __restrict__ bsum,
        float* __restrict__ out, int s) {
    int row0 = blockIdx.x * 64;      // over 8*1024 rows
    int b = row0 >> 10;
    int n0 = row0 & 1023;
    __shared__ float As[64][68];
    __shared__ float Bs[64][68];
    int tid = threadIdx.x;
    int tx = tid & 15, ty = tid >> 4;
    float acc[4][4] = {};
    for (int j = 0; j < 6; j++) {
        loadA_T(As, &cur[(((size_t)b * 23 + s + 5 + j) * NN + n0) * 64], 64, tid);
        loadB_D(Bs, &wcT[(size_t)j * 64 * 64], 64, tid);
        __syncthreads();
        mm64(As, Bs, acc, tx, ty);
        __syncthreads();
    }
    const float inv6 = 1.f / 6.f;
#pragma unroll
    for (int i = 0; i < 4; i++) {
        int m = row0 + ty * 4 + i;
#pragma unroll
        for (int j = 0; j < 4; j++) {
            int d = tx * 4 + j;
            out[(size_t)m * 64 + d] = (acc[i][j] + bsum[d]) * inv6;
        }
    }
}

// ================= AR cur-buffer init: cur[:,0:11] = res[:,31:42] =================
__global__ void k_cur_init(const float* __restrict__ res, float* __restrict__ cur) {
    size_t total = (size_t)NB * MAXK * NN * 64;
    for (size_t idx = (size_t)blockIdx.x * blockDim.x + threadIdx.x; idx < total;
         idx += (size_t)gridDim.x * blockDim.x) {
        int d = idx & 63;
        int n = (idx >> 6) & 1023;
        int j = (int)((idx >> 16) % MAXK);
        int b = (int)(idx / ((size_t)MAXK << 16));
        cur[(((size_t)b * 23 + j) * NN + n) * 64 + d] =
            res[(((size_t)b * FREQ + 31 + j) * NN + n) * 64 + d];
    }
}

// ================= decoder MLP for rec =================
__global__ void __launch_bounds__(256) k_dec_rec(const float* __restrict__ res,
        const float* __restrict__ stout,
        const float* __restrict__ w1, const float* __restrict__ b1,
        const float* __restrict__ w2, const float* __restrict__ b2,
        float* __restrict__ out) {
    int n0 = blockIdx.x * 64;
    int f  = blockIdx.y;
    int b  = blockIdx.z;
    const float* src = (f == 0)
        ? &res[(((size_t)b * FREQ) * NN + n0) * 64]
        : &stout[(((size_t)b * TREC + f - 1) * NN + n0) * 64];
    __shared__ float hs[64][129];
    int tid = threadIdx.x;
    {
        int r = tid >> 2;
        int j0 = (tid & 3) * 32;
        const float* xr = &src[(size_t)r * 64];
        for (int j = j0; j < j0 + 32; j++) {
            float h = b1[j];
#pragma unroll
            for (int c = 0; c < 64; c++) h = fmaf(xr[c], w1[c * 128 + j], h);
            hs[r][j] = fmaxf(h, 0.f);
        }
    }
    __syncthreads();
    for (int o = tid; o < 512; o += 256) {
        int r = o & 63, s = o >> 6;
        float acc = b2[s];
#pragma unroll
        for (int j = 0; j < 128; j++) acc = fmaf(hs[r][j], w2[j * 8 + s], acc);
        out[((size_t)b * NT + f * SEG + s) * NN + n0 + r] = acc;
    }
}

// ================= decoder MLP for pred (with the reference's direct reshape) =================
// pred flat per batch: t*8192 + n*8 + s
__global__ void __launch_bounds__(256) k_dec_pred(const float* __restrict__ cur,
        const float* __restrict__ w1, const float* __restrict__ b1,
        const float* __restrict__ w2, const float* __restrict__ b2,
        float* __restrict__ out) {
    int n0 = blockIdx.x * 64;
    int t  = blockIdx.y;
    int b  = blockIdx.z;
    const float* src = &cur[(((size_t)b * 23 + MAXK + t) * NN + n0) * 64];
    __shared__ float hs[64][129];
    int tid = threadIdx.x;
    {
        int r = tid >> 2;
        int j0 = (tid & 3) * 32;
        const float* xr = &src[(size_t)r * 64];
        for (int j = j0; j < j0 + 32; j++) {
            float h = b1[j];
#pragma unroll
            for (int c = 0; c < 64; c++) h = fmaf(xr[c], w1[c * 128 + j], h);
            hs[r][j] = fmaxf(h, 0.f);
        }
    }
    __syncthreads();
    for (int o = tid; o < 512; o += 256) {
        int r = o >> 3, s = o & 7;
        float acc = b2[s];
#pragma unroll
        for (int j = 0; j < 128; j++) acc = fmaf(hs[r][j], w2[j * 8 + s], acc);
        out[(size_t)b * (NSTEP * SEG * NN) + (size_t)t * 8192 + (size_t)(n0 + r) * 8 + s] = acc;
    }
}

// ================= host launcher =================
extern "C" void kernel_launch(void* const* d_in, const int* in_sizes, int n_in,
                              void* d_out, int out_size) {
    (void)in_sizes; (void)n_in; (void)out_size;
    const float* x_diff = (const float*)d_in[0];
    const float* adj    = (const float*)d_in[1];
    const float* enc_w1 = (const float*)d_in[2];
    const float* enc_b1 = (const float*)d_in[3];
    const float* enc_w2 = (const float*)d_in[4];
    const float* enc_b2 = (const float*)d_in[5];
    const float* dec_w1 = (const float*)d_in[6];
    const float* dec_b1 = (const float*)d_in[7];
    const float* dec_w2 = (const float*)d_in[8];
    const float* dec_b2 = (const float*)d_in[9];
    const float* g1_w   = (const float*)d_in[10];
    const float* g1_b   = (const float*)d_in[11];
    const float* g2_w   = (const float*)d_in[12];
    const float* g2_b   = (const float*)d_in[13];
    const float* cw[6], *cb[6];
    for (int i = 0; i < 6; i++) {
        cw[i] = (const float*)d_in[14 + 2 * i];
        cb[i] = (const float*)d_in[15 + 2 * i];
    }

    float* scratch = nullptr;
    cudaGetSymbolAddress((void**)&scratch, g_scratch);
    float* a1    = scratch + OFF_A1;
    float* a2    = scratch + OFF_A2;
    float* wcT   = scratch + OFF_WCT;
    float* bsum  = scratch + OFF_BSUM;
    float* res   = scratch + OFF_RES;
    float* conv  = scratch + OFF_CONV;
    float* h1a   = scratch + OFF_H1A;
    float* h2a   = scratch + OFF_H2A;
    float* h1b   = scratch + OFF_H1B;
    float* h2b   = scratch + OFF_H2B;
    float* stout = scratch + OFF_STOUT;
    float* cur   = scratch + OFF_CUR;
    float* tcl   = scratch + OFF_TCL;
    float* ph1a  = scratch + OFF_PH1A;
    float* ph1b  = scratch + OFF_PH1B;
    float* ph2a  = scratch + OFF_PH2A;
    float* ph2b  = scratch + OFF_PH2B;

    float* rec_out  = (float*)d_out;
    float* pred_out = rec_out + (size_t)NB * NT * NN;

    // ---- preprocessing ----
    k_norm_adj<<<NN, 256>>>(adj, a1, a2);
    k_comb_w<<<(11 * 64 * 64 + 255) / 256, 256>>>(cw[0], cw[1], cw[2], cw[3], cw[4], cw[5],
                                                  cb[0], cb[1], cb[2], cb[3], cb[4], cb[5],
                                                  wcT, bsum);
    // ---- encoder ----
    k_enc<<<dim3(16, FREQ, NB), 256>>>(x_diff, enc_w1, enc_b1, enc_w2, enc_b2, res);

    // ---- rec-path stconv ----
    dim3 gRec(16, NB * TREC);
    k_tconv<<<gRec, 256>>>(res, wcT, bsum, conv);
    k_prop<<<gRec, 256>>>(a1, conv, conv, h1a);
    k_prop<<<gRec, 256>>>(a2, conv, conv, h1b);
    k_prop<<<gRec, 256>>>(a1, h1a, conv, h2a);
    k_prop<<<gRec, 256>>>(a2, h1b, conv, h2b);
    k_combine<<<gRec, 256>>>(conv, h1a, h2a, h1b, h2b, g1_w, g1_b, g2_w, g2_b,
                             res, stout,
                             TREC, FREQ, 0,     // resid row = b*42 + t
                             TREC, TREC, 0);    // out   row = bt
    // ---- rec decoder ----
    k_dec_rec<<<dim3(16, FREQ, NB), 256>>>(res, stout, dec_w1, dec_b1, dec_w2, dec_b2, rec_out);

    // ---- autoregressive loop ----
    k_cur_init<<<4096, 256>>>(res, cur);
    dim3 gAR(16, NB);
    for (int s = 0; s < NSTEP; s++) {
        k_tcl<<<128, 256>>>(cur, wcT, bsum, tcl, s);
        k_prop<<<gAR, 256>>>(a1, tcl, tcl, ph1a);
        k_prop<<<gAR, 256>>>(a2, tcl, tcl, ph1b);
        k_prop<<<gAR, 256>>>(a1, ph1a, tcl, ph2a);
        k_prop<<<gAR, 256>>>(a2, ph1b, tcl, ph2b);
        k_combine<<<gAR, 256>>>(tcl, ph1a, ph2a, ph1b, ph2b, g1_w, g1_b, g2_w, g2_b,
                                cur, cur,
                                1, 23, s + 10,   // resid row = b*23 + s+10
                                1, 23, s + 11);  // out   row = b*23 + s+11
    }
    // ---- pred decoder ----
    k_dec_pred<<<dim3(16, NSTEP, NB), 256>>>(cur, dec_w1, dec_b1, dec_w2, dec_b2, pred_out);
}